// round 5
// baseline (speedup 1.0000x reference)
#include <cuda_runtime.h>
#include <cstdint>

// Gini of n=8192 fp32 vector, single fused launch.
//
// sum_{i,j}|xi-xj| is shift-invariant => min-shift only affects mu.
// 16x16 triangular tiling (136 tiles of 512x512, off-diag weighted 2x),
// 4 column strips of 128 per tile => 544 pair blocks + 1 min/sum block.
//
// Math per 2 packed pairs: FFMA2 diff (c*(-1)+r), AND64 abs (alu pipe),
// FFMA2 accumulate (|d|*1+acc). fma.rn.f32x2 is the packed-SASS path.
// Deterministic: shfl butterfly + fixed-order block partial reduce.

#define T_CHUNKS 16
#define CHUNK    512
#define STRIPS   4
#define SCOLS    (CHUNK / STRIPS)                 // 128
#define NTILES   (T_CHUNKS * (T_CHUNKS + 1) / 2)  // 136
#define NPAIRBLK (NTILES * STRIPS)                // 544
#define THREADS  256
#define GEN_MAX  4096

__device__ float        g_part[NPAIRBLK > GEN_MAX ? NPAIRBLK : GEN_MAX];
__device__ float        g_min_val;
__device__ float        g_sum_val;
__device__ unsigned int g_count = 0;

__device__ __forceinline__ uint64_t pack2(float lo, float hi) {
    uint64_t r;
    asm("mov.b64 %0, {%1, %2};" : "=l"(r) : "f"(lo), "f"(hi));
    return r;
}
__device__ __forceinline__ uint64_t fma2(uint64_t a, uint64_t b, uint64_t c) {
    uint64_t r;
    asm("fma.rn.f32x2 %0, %1, %2, %3;" : "=l"(r) : "l"(a), "l"(b), "l"(c));
    return r;
}
__device__ __forceinline__ float unpack_sum(uint64_t a) {
    float lo, hi;
    asm("mov.b64 {%0, %1}, %2;" : "=f"(lo), "=f"(hi) : "l"(a));
    return lo + hi;
}
__device__ __forceinline__ float warp_sum(float v) {
#pragma unroll
    for (int off = 16; off > 0; off >>= 1)
        v += __shfl_xor_sync(0xFFFFFFFFu, v, off);
    return v;
}
__device__ __forceinline__ float warp_min(float v) {
#pragma unroll
    for (int off = 16; off > 0; off >>= 1)
        v = fminf(v, __shfl_xor_sync(0xFFFFFFFFu, v, off));
    return v;
}

// fixed-order reduce of nblk partials + closed form; resets counter
__device__ __forceinline__ void finalize_last(int n, float* __restrict__ out,
                                              int nblk, float* red) {
    const int tid = threadIdx.x;
    float s = 0.0f;
    for (int i = tid; i < nblk; i += THREADS) s += g_part[i];
    s = warp_sum(s);
    if ((tid & 31) == 0) red[tid >> 5] = s;
    __syncthreads();
    if (tid == 0) {
        float S = 0.0f;
#pragma unroll
        for (int w = 0; w < THREADS / 32; ++w) S += red[w];
        const float nf = (float)n;
        float mean = g_sum_val / nf;
        float mn = g_min_val;
        if (mn < 0.0f) mean -= mn;                 // mean(x - min)
        out[0] = S / (2.0f * nf * nf * (mean + 1e-8f));
        g_count = 0;                               // reset for graph replay
    }
}

// ---------------- fused kernel (n == 8192 path) ----------------
__global__ __launch_bounds__(THREADS)
void k_gini(const float* __restrict__ x, float* __restrict__ out, int n) {
    __shared__ float4 shv[SCOLS / 4];              // raw column strip (512 B)
    __shared__ float  red[THREADS / 32];
    __shared__ unsigned int isLast;

    const int tid = threadIdx.x;
    const int b   = blockIdx.x;

    if (b == 0) {
        // -------- min + sum block (overlaps with pairwise blocks) --------
        __shared__ float smins[THREADS / 32];
        float mn = 3.402823466e38f, sm = 0.0f;
        const int nv4 = n / 4;
        for (int i = tid; i < nv4; i += THREADS) {
            float4 v = reinterpret_cast<const float4*>(x)[i];
            mn = fminf(mn, fminf(fminf(v.x, v.y), fminf(v.z, v.w)));
            sm += (v.x + v.y) + (v.z + v.w);
        }
        sm = warp_sum(sm);
        mn = warp_min(mn);
        if ((tid & 31) == 0) { red[tid >> 5] = sm; smins[tid >> 5] = mn; }
        __syncthreads();
        if (tid == 0) {
            float S = 0.0f, M = 3.402823466e38f;
#pragma unroll
            for (int w = 0; w < THREADS / 32; ++w) { S += red[w]; M = fminf(M, smins[w]); }
            g_min_val = M;
            g_sum_val = S;
            __threadfence();
            unsigned int c = atomicAdd(&g_count, 1u);
            isLast = (c == gridDim.x - 1) ? 1u : 0u;
        }
        __syncthreads();
        if (isLast) { __threadfence(); finalize_last(n, out, NPAIRBLK, red); }
        return;
    }

    // -------- pairwise tile strip --------
    const int t     = b - 1;
    const int strip = t & (STRIPS - 1);
    int rc = 0, rem = t >> 2;                      // tile -> (rc, cc), rc <= cc
    while (rem >= T_CHUNKS - rc) { rem -= (T_CHUNKS - rc); rc++; }
    const int cc = rc + rem;
    const int colBase = cc * CHUNK + strip * SCOLS;
    const int rowBase = rc * CHUNK;

    // column strip into smem (32 threads x float4, coalesced)
    if (tid < SCOLS / 4)
        shv[tid] = reinterpret_cast<const float4*>(x + colBase)[tid];
    const float r0 = x[rowBase + tid];
    const float r1 = x[rowBase + THREADS + tid];
    const uint64_t rp0 = pack2(r0, r0);
    const uint64_t rp1 = pack2(r1, r1);
    __syncthreads();

    const uint64_t MASK = 0x7FFFFFFF7FFFFFFFULL;
    const uint64_t NEG1 = pack2(-1.0f, -1.0f);
    const uint64_t ONE1 = pack2(1.0f, 1.0f);
    uint64_t a00 = 0, a01 = 0, a10 = 0, a11 = 0;   // 4 independent chains
    const ulonglong2* shq = reinterpret_cast<const ulonglong2*>(shv);

#pragma unroll
    for (int j = 0; j < SCOLS / 4; ++j) {          // 32 iters, 4 cols each
        const ulonglong2 c = shq[j];               // LDS.128 broadcast
        uint64_t d00 = fma2(c.x, NEG1, rp0) & MASK;   // |r0 - c|
        uint64_t d01 = fma2(c.y, NEG1, rp0) & MASK;
        uint64_t d10 = fma2(c.x, NEG1, rp1) & MASK;
        uint64_t d11 = fma2(c.y, NEG1, rp1) & MASK;
        a00 = fma2(d00, ONE1, a00);
        a01 = fma2(d01, ONE1, a01);
        a10 = fma2(d10, ONE1, a10);
        a11 = fma2(d11, ONE1, a11);
    }

    float mysum = unpack_sum(fma2(a00, ONE1, a01)) + unpack_sum(fma2(a10, ONE1, a11));

    mysum = warp_sum(mysum);
    if ((tid & 31) == 0) red[tid >> 5] = mysum;
    __syncthreads();
    if (tid == 0) {
        float p = 0.0f;
#pragma unroll
        for (int w = 0; w < THREADS / 32; ++w) p += red[w];
        if (rc != cc) p *= 2.0f;                   // symmetry weight
        g_part[t] = p;
        __threadfence();
        unsigned int c = atomicAdd(&g_count, 1u);
        isLast = (c == gridDim.x - 1) ? 1u : 0u;
    }
    __syncthreads();
    if (isLast) { __threadfence(); finalize_last(n, out, NPAIRBLK, red); }
}

// ---------------- generic fallback (any n) ----------------
__global__ void k_gini_generic(const float* __restrict__ x, float* __restrict__ out, int n) {
    __shared__ float red[THREADS];
    __shared__ float smin[THREADS];
    __shared__ unsigned int isLast;
    const int tid = threadIdx.x;
    const int i = blockIdx.x * THREADS + tid;
    float a = 0.0f;
    if (i < n) {
        const float xi = x[i];
        for (int j = 0; j < n; ++j) a += fabsf(xi - x[j]);
    }
    red[tid] = a;
    __syncthreads();
    for (int off = THREADS / 2; off > 0; off >>= 1) {
        if (tid < off) red[tid] += red[tid + off];
        __syncthreads();
    }
    if (tid == 0) {
        g_part[blockIdx.x] = red[0];
        __threadfence();
        unsigned int c = atomicAdd(&g_count, 1u);
        isLast = (c == gridDim.x - 1) ? 1u : 0u;
    }
    __syncthreads();
    if (isLast) {
        __threadfence();
        float mn = 3.402823466e38f, sm = 0.0f;
        for (int k = tid; k < n; k += THREADS) {
            float v = x[k];
            mn = fminf(mn, v);
            sm += v;
        }
        red[tid] = sm; smin[tid] = mn;
        __syncthreads();
        for (int off = THREADS / 2; off > 0; off >>= 1) {
            if (tid < off) {
                red[tid] += red[tid + off];
                smin[tid] = fminf(smin[tid], smin[tid + off]);
            }
            __syncthreads();
        }
        if (tid == 0) { g_min_val = smin[0]; g_sum_val = red[0]; }
        __syncthreads();
        float s = 0.0f;
        for (int k = tid; k < gridDim.x; k += THREADS) s += g_part[k];
        red[tid] = s;
        __syncthreads();
        for (int off = THREADS / 2; off > 0; off >>= 1) {
            if (tid < off) red[tid] += red[tid + off];
            __syncthreads();
        }
        if (tid == 0) {
            const float nf = (float)n;
            float mean = g_sum_val / nf;
            if (g_min_val < 0.0f) mean -= g_min_val;
            out[0] = red[0] / (2.0f * nf * nf * (mean + 1e-8f));
            g_count = 0;
        }
    }
}

extern "C" void kernel_launch(void* const* d_in, const int* in_sizes, int n_in,
                              void* d_out, int out_size) {
    const float* x = (const float*)d_in[0];
    float* out = (float*)d_out;
    const int n = in_sizes[0];

    if (n == T_CHUNKS * CHUNK) {
        k_gini<<<NPAIRBLK + 1, THREADS>>>(x, out, n);
    } else {
        int nblk = (n + THREADS - 1) / THREADS;
        if (nblk > GEN_MAX) nblk = GEN_MAX;
        k_gini_generic<<<nblk, THREADS>>>(x, out, n);
    }
}

// round 6
// speedup vs baseline: 1.4090x; 1.4090x over previous
#include <cuda_runtime.h>
#include <cstdint>

// Gini of n=8192 fp32 vector, single fused launch.
//
// sum_{i,j}|xi-xj| is shift-invariant => min-shift only affects mu.
// 16x16 triangular tiling (136 tiles of 512x512, off-diag weighted 2x),
// 4 column strips of 128 per tile => 544 pair blocks + 1 min/sum block.
//
// Scalar math only (packed f32x2 splits on this ptxas and adds MOV bloat):
//   diff: FFMA-imm  d = c*(-1) + r        (fma pipe, rt_SMSP=1)
//   acc:  FADD a, a, |d|  (abs folded into operand modifier, rt_SMSP=2)
// 8 independent accumulator chains; shfl-butterfly epilogue.

#define T_CHUNKS 16
#define CHUNK    512
#define STRIPS   4
#define SCOLS    (CHUNK / STRIPS)                 // 128
#define NTILES   (T_CHUNKS * (T_CHUNKS + 1) / 2)  // 136
#define NPAIRBLK (NTILES * STRIPS)                // 544
#define THREADS  256
#define GEN_MAX  4096

__device__ float        g_part[NPAIRBLK > GEN_MAX ? NPAIRBLK : GEN_MAX];
__device__ float        g_min_val;
__device__ float        g_sum_val;
__device__ unsigned int g_count = 0;

// FFMA src1-imm form (rt_SMSP=1): d = c * (-1.0f) + r
__device__ __forceinline__ float diff_ffma(float c, float r) {
    float d;
    asm("fma.rn.f32 %0, %1, 0fBF800000, %2;" : "=f"(d) : "f"(c), "f"(r));
    return d;
}

__device__ __forceinline__ float warp_sum(float v) {
#pragma unroll
    for (int off = 16; off > 0; off >>= 1)
        v += __shfl_xor_sync(0xFFFFFFFFu, v, off);
    return v;
}
__device__ __forceinline__ float warp_min(float v) {
#pragma unroll
    for (int off = 16; off > 0; off >>= 1)
        v = fminf(v, __shfl_xor_sync(0xFFFFFFFFu, v, off));
    return v;
}

// fixed-order reduce of nblk partials + closed form; resets counter
__device__ __forceinline__ void finalize_last(int n, float* __restrict__ out,
                                              int nblk, float* red) {
    const int tid = threadIdx.x;
    float s = 0.0f;
    for (int i = tid; i < nblk; i += THREADS) s += g_part[i];
    s = warp_sum(s);
    if ((tid & 31) == 0) red[tid >> 5] = s;
    __syncthreads();
    if (tid == 0) {
        float S = 0.0f;
#pragma unroll
        for (int w = 0; w < THREADS / 32; ++w) S += red[w];
        const float nf = (float)n;
        float mean = g_sum_val / nf;
        float mn = g_min_val;
        if (mn < 0.0f) mean -= mn;                 // mean(x - min)
        out[0] = S / (2.0f * nf * nf * (mean + 1e-8f));
        g_count = 0;                               // reset for graph replay
    }
}

// ---------------- fused kernel (n == 8192 path) ----------------
__global__ __launch_bounds__(THREADS)
void k_gini(const float* __restrict__ x, float* __restrict__ out, int n) {
    __shared__ float4 shv[SCOLS / 4];              // column strip (512 B)
    __shared__ float  red[THREADS / 32];
    __shared__ unsigned int isLast;

    const int tid = threadIdx.x;
    const int b   = blockIdx.x;

    if (b == 0) {
        // -------- min + sum block (overlaps with pairwise blocks) --------
        __shared__ float smins[THREADS / 32];
        float mn = 3.402823466e38f, sm = 0.0f;
        const int nv4 = n / 4;
        for (int i = tid; i < nv4; i += THREADS) {
            float4 v = reinterpret_cast<const float4*>(x)[i];
            mn = fminf(mn, fminf(fminf(v.x, v.y), fminf(v.z, v.w)));
            sm += (v.x + v.y) + (v.z + v.w);
        }
        sm = warp_sum(sm);
        mn = warp_min(mn);
        if ((tid & 31) == 0) { red[tid >> 5] = sm; smins[tid >> 5] = mn; }
        __syncthreads();
        if (tid == 0) {
            float S = 0.0f, M = 3.402823466e38f;
#pragma unroll
            for (int w = 0; w < THREADS / 32; ++w) { S += red[w]; M = fminf(M, smins[w]); }
            g_min_val = M;
            g_sum_val = S;
            __threadfence();
            unsigned int c = atomicAdd(&g_count, 1u);
            isLast = (c == gridDim.x - 1) ? 1u : 0u;
        }
        __syncthreads();
        if (isLast) { __threadfence(); finalize_last(n, out, NPAIRBLK, red); }
        return;
    }

    // -------- pairwise tile strip --------
    const int t     = b - 1;
    const int strip = t & (STRIPS - 1);
    int rc = 0, rem = t >> 2;                      // tile -> (rc, cc), rc <= cc
    while (rem >= T_CHUNKS - rc) { rem -= (T_CHUNKS - rc); rc++; }
    const int cc = rc + rem;
    const int colBase = cc * CHUNK + strip * SCOLS;
    const int rowBase = rc * CHUNK;

    // column strip into smem (32 threads x float4, coalesced)
    if (tid < SCOLS / 4)
        shv[tid] = reinterpret_cast<const float4*>(x + colBase)[tid];
    const float r0 = x[rowBase + tid];
    const float r1 = x[rowBase + THREADS + tid];
    __syncthreads();

    // 8 independent accumulator chains (one per pair slot per iter)
    float a0 = 0.f, a1 = 0.f, a2 = 0.f, a3 = 0.f;
    float a4 = 0.f, a5 = 0.f, a6 = 0.f, a7 = 0.f;

#pragma unroll
    for (int j = 0; j < SCOLS / 4; ++j) {          // 32 iters, 4 cols x 2 rows
        const float4 c = shv[j];                   // LDS.128 broadcast
        a0 += fabsf(diff_ffma(c.x, r0));
        a1 += fabsf(diff_ffma(c.y, r0));
        a2 += fabsf(diff_ffma(c.z, r0));
        a3 += fabsf(diff_ffma(c.w, r0));
        a4 += fabsf(diff_ffma(c.x, r1));
        a5 += fabsf(diff_ffma(c.y, r1));
        a6 += fabsf(diff_ffma(c.z, r1));
        a7 += fabsf(diff_ffma(c.w, r1));
    }

    float mysum = ((a0 + a1) + (a2 + a3)) + ((a4 + a5) + (a6 + a7));

    mysum = warp_sum(mysum);
    if ((tid & 31) == 0) red[tid >> 5] = mysum;
    __syncthreads();
    if (tid == 0) {
        float p = 0.0f;
#pragma unroll
        for (int w = 0; w < THREADS / 32; ++w) p += red[w];
        if (rc != cc) p *= 2.0f;                   // symmetry weight
        g_part[t] = p;
        __threadfence();
        unsigned int c = atomicAdd(&g_count, 1u);
        isLast = (c == gridDim.x - 1) ? 1u : 0u;
    }
    __syncthreads();
    if (isLast) { __threadfence(); finalize_last(n, out, NPAIRBLK, red); }
}

// ---------------- generic fallback (any n) ----------------
__global__ void k_gini_generic(const float* __restrict__ x, float* __restrict__ out, int n) {
    __shared__ float red[THREADS];
    __shared__ float smin[THREADS];
    __shared__ unsigned int isLast;
    const int tid = threadIdx.x;
    const int i = blockIdx.x * THREADS + tid;
    float a = 0.0f;
    if (i < n) {
        const float xi = x[i];
        for (int j = 0; j < n; ++j) a += fabsf(xi - x[j]);
    }
    red[tid] = a;
    __syncthreads();
    for (int off = THREADS / 2; off > 0; off >>= 1) {
        if (tid < off) red[tid] += red[tid + off];
        __syncthreads();
    }
    if (tid == 0) {
        g_part[blockIdx.x] = red[0];
        __threadfence();
        unsigned int c = atomicAdd(&g_count, 1u);
        isLast = (c == gridDim.x - 1) ? 1u : 0u;
    }
    __syncthreads();
    if (isLast) {
        __threadfence();
        float mn = 3.402823466e38f, sm = 0.0f;
        for (int k = tid; k < n; k += THREADS) {
            float v = x[k];
            mn = fminf(mn, v);
            sm += v;
        }
        red[tid] = sm; smin[tid] = mn;
        __syncthreads();
        for (int off = THREADS / 2; off > 0; off >>= 1) {
            if (tid < off) {
                red[tid] += red[tid + off];
                smin[tid] = fminf(smin[tid], smin[tid + off]);
            }
            __syncthreads();
        }
        if (tid == 0) { g_min_val = smin[0]; g_sum_val = red[0]; }
        __syncthreads();
        float s = 0.0f;
        for (int k = tid; k < gridDim.x; k += THREADS) s += g_part[k];
        red[tid] = s;
        __syncthreads();
        for (int off = THREADS / 2; off > 0; off >>= 1) {
            if (tid < off) red[tid] += red[tid + off];
            __syncthreads();
        }
        if (tid == 0) {
            const float nf = (float)n;
            float mean = g_sum_val / nf;
            if (g_min_val < 0.0f) mean -= g_min_val;
            out[0] = red[0] / (2.0f * nf * nf * (mean + 1e-8f));
            g_count = 0;
        }
    }
}

extern "C" void kernel_launch(void* const* d_in, const int* in_sizes, int n_in,
                              void* d_out, int out_size) {
    const float* x = (const float*)d_in[0];
    float* out = (float*)d_out;
    const int n = in_sizes[0];

    if (n == T_CHUNKS * CHUNK) {
        k_gini<<<NPAIRBLK + 1, THREADS>>>(x, out, n);
    } else {
        int nblk = (n + THREADS - 1) / THREADS;
        if (nblk > GEN_MAX) nblk = GEN_MAX;
        k_gini_generic<<<nblk, THREADS>>>(x, out, n);
    }
}